// round 10
// baseline (speedup 1.0000x reference)
#include <cuda_runtime.h>
#include <cuda_fp16.h>
#include <math.h>
#include <stdint.h>

#define N_NODES 32767
#define HDIM 256
#define H2 512
#define G4 2048
#define VOCAB 32
#define LEAF0 16383
#define NPAR 16384            // parents 0..16382 (+1 pad)

// ---------------- device state / tables ----------------
__device__ __half g_Acat[(size_t)NPAR * H2];    // concat child-h per parent (fp16)
__device__ float  g_Ccat[(size_t)NPAR * H2];    // concat child-c per parent (fp32)
__device__ float  g_xtabp[VOCAB * G4];          // permuted jj = hid*4+g
__device__ __half g_Wh[G4 * H2];                // permuted rows [jj][k] fp16 (tc B)
__device__ float  g_WhTp[H2 * G4];              // permuted k-major [k][jj] fp32 (small)
__device__ float  g_ltab_h[VOCAB * H2];
__device__ float  g_ltab_c[VOCAB * HDIM];
__device__ __half g_ltab_h16[VOCAB * HDIM];
__device__ unsigned g_barcnt = 0;               // grid barrier state (invariant: 0 between barriers)
__device__ unsigned g_bargen = 0;

__device__ __forceinline__ float tanh_fast(float x) {
    float y;
    asm("tanh.approx.f32 %0, %1;" : "=f"(y) : "f"(x));
    return y;
}
__device__ __forceinline__ float sigm_fast(float x) {
    return fmaf(0.5f, tanh_fast(0.5f * x), 0.5f);
}

__device__ __forceinline__ uint32_t smem_u32(const void* p) {
    uint32_t a;
    asm("{ .reg .u64 t; cvta.to.shared.u64 t, %1; cvt.u32.u64 %0, t; }" : "=r"(a) : "l"(p));
    return a;
}
__device__ __forceinline__ void cpa16(uint32_t dst, const void* src) {
    asm volatile("cp.async.cg.shared.global [%0], [%1], 16;" :: "r"(dst), "l"(src));
}
__device__ __forceinline__ void cp_commit() { asm volatile("cp.async.commit_group;"); }
__device__ __forceinline__ void cp_wait1() { asm volatile("cp.async.wait_group 1;"); }
__device__ __forceinline__ void cp_wait0() { asm volatile("cp.async.wait_group 0;"); }

__device__ __forceinline__ void ldmatrix4(uint32_t& r0, uint32_t& r1, uint32_t& r2, uint32_t& r3,
                                          uint32_t addr) {
    asm volatile("ldmatrix.sync.aligned.m8n8.x4.shared.b16 {%0,%1,%2,%3}, [%4];"
                 : "=r"(r0), "=r"(r1), "=r"(r2), "=r"(r3) : "r"(addr));
}
__device__ __forceinline__ void mma16816(float& d0, float& d1, float& d2, float& d3,
                                         uint32_t a0, uint32_t a1, uint32_t a2, uint32_t a3,
                                         uint32_t b0, uint32_t b1) {
    asm volatile(
        "mma.sync.aligned.m16n8k16.row.col.f32.f16.f16.f32 "
        "{%0,%1,%2,%3}, {%4,%5,%6,%7}, {%8,%9}, {%0,%1,%2,%3};"
        : "+f"(d0), "+f"(d1), "+f"(d2), "+f"(d3)
        : "r"(a0), "r"(a1), "r"(a2), "r"(a3), "r"(b0), "r"(b1));
}

#define SWZ(x) ((x) ^ (((x) >> 3) & 0x70))

// ---------------- tc smem layout ----------------
#define OFF_META   0
#define OFF_STAGE  2048
#define A_BYTES    16384
#define B_STRIDE   144
#define B_BYTES    (64 * B_STRIDE)
#define STAGE_SZ   (A_BYTES + B_BYTES)
#define ST_A       0
#define ST_B       A_BYTES
#define SMEM_DYN   (OFF_STAGE + 2 * STAGE_SZ)   // 53248 -> 4 CTAs/SM
#define GST        68

// ---------------- prep: x table (permuted) + leaf tables ----------------
__global__ __launch_bounds__(256) void xtab_kernel(const float* __restrict__ emb,
                                                   const float* __restrict__ W_ih,
                                                   const float* __restrict__ b_ih,
                                                   const float* __restrict__ b_hh) {
    __shared__ float se[256];
    __shared__ float sx[G4];
    int v = blockIdx.x;
    int t = threadIdx.x;
    se[t] = emb[v * 256 + t];
    __syncthreads();
    #pragma unroll
    for (int m = 0; m < 8; m++) {
        int j = m * 256 + t;
        float acc = b_ih[j] + b_hh[j];
        const float4* wr = (const float4*)(W_ih + j * 256);
        #pragma unroll 8
        for (int k4 = 0; k4 < 64; k4++) {
            float4 w = wr[k4];
            acc += w.x * se[k4 * 4 + 0] + w.y * se[k4 * 4 + 1]
                 + w.z * se[k4 * 4 + 2] + w.w * se[k4 * 4 + 3];
        }
        g_xtabp[v * G4 + (j & 511) * 4 + (j >> 9)] = acc;
        sx[j] = acc;
    }
    __syncthreads();
    #pragma unroll
    for (int q = 0; q < 2; q++) {
        int hid = q * 256 + t;
        float ig = sx[hid];
        float gg = sx[1024 + hid];
        float og = sx[1536 + hid];
        float cn = sigm_fast(ig) * tanh_fast(gg);
        float hn = sigm_fast(og) * tanh_fast(cn);
        g_ltab_h[v * H2 + hid] = hn;
        if (q == 0) {
            g_ltab_c[v * HDIM + t] = cn;
            g_ltab_h16[v * HDIM + t] = __float2half_rn(hn);
        }
    }
}

// ---------------- prep: fp16 permuted rows + fp32 permuted k-major ----------------
__global__ void wprep_kernel(const float* __restrict__ W_hh) {
    __shared__ float tile[32][33];
    int j0 = blockIdx.x * 32;
    int k0 = blockIdx.y * 32;
    int tx = threadIdx.x, ty = threadIdx.y;
    #pragma unroll
    for (int r = 0; r < 32; r += 8) {
        int j = j0 + ty + r;
        float w = W_hh[j * H2 + k0 + tx];
        tile[ty + r][tx] = w;
        int jj = (j & 511) * 4 + (j >> 9);
        g_Wh[(size_t)jj * H2 + k0 + tx] = __float2half_rn(w);
    }
    __syncthreads();
    #pragma unroll
    for (int r = 0; r < 32; r += 8) {
        int j = j0 + tx;
        int jj = (j & 511) * 4 + (j >> 9);
        g_WhTp[(size_t)(k0 + ty + r) * G4 + jj] = tile[tx][ty + r];
    }
}

// ---------------- leaves: table copy, scatter into parent-staged buffers ----------------
__global__ __launch_bounds__(256) void leaf_kernel(const int* __restrict__ types,
                                                   float* __restrict__ out) {
    int wid = threadIdx.x >> 5;
    int lane = threadIdx.x & 31;
    int node = LEAF0 + blockIdx.x * 8 + wid;
    if (node >= N_NODES) return;
    int v = types[node];
    const float4* sh = (const float4*)(g_ltab_h + (size_t)v * H2);
    float4* dh = (float4*)(out + (size_t)node * H2);
    #pragma unroll
    for (int q = 0; q < 4; q++) dh[lane + 32 * q] = sh[lane + 32 * q];
    int parent = (node - 1) >> 1;
    int off = (node & 1) ? 0 : 256;
    const uint4* s16 = (const uint4*)(g_ltab_h16 + (size_t)v * HDIM);
    uint4* d16 = (uint4*)(g_Acat + (size_t)parent * H2 + off);
    d16[lane] = s16[lane];
    const float4* sc = (const float4*)(g_ltab_c + (size_t)v * HDIM);
    float4* dc = (float4*)(g_Ccat + (size_t)parent * H2 + off);
    #pragma unroll
    for (int q = 0; q < 2; q++) dc[lane + 32 * q] = sc[lane + 32 * q];
}

// ---------------- HMMA level kernel: M=128 x N=64 x K=512, dense A (levels 13..9) ----------------
__global__ __launch_bounds__(256, 4) void tc_level_kernel(
    const int* __restrict__ types, float* __restrict__ out, int s) {
    extern __shared__ char sp[];
    uint32_t sbase = smem_u32(sp);
    int tid = threadIdx.x;
    int lane = tid & 31;
    int wid = tid >> 5;
    int wm = wid >> 2;
    int wn = wid & 3;
    int by = blockIdx.y;
    int base = s + blockIdx.x * 128;

    int* sty = (int*)(sp + OFF_META);
    if (tid < 128) sty[tid] = types[base + tid];
    __syncthreads();

    int arow = tid >> 1, ahalf = tid & 1;
    int brow = tid >> 2, bq = tid & 3;

    auto load_chunk = [&](int kc, int st) {
        uint32_t stg = sbase + OFF_STAGE + st * STAGE_SZ;
        // A: dense per-parent concat rows
        const char* ah = (const char*)(g_Acat + (size_t)(base + arow) * H2 + kc * 64) + ahalf * 64;
        #pragma unroll
        for (int q = 0; q < 4; q++) {
            uint32_t boff = arow * 128 + ahalf * 64 + q * 16;
            cpa16(stg + ST_A + SWZ(boff), ah + q * 16);
        }
        const char* wh = (const char*)(g_Wh + (size_t)(by * 64 + brow) * H2 + kc * 64) + bq * 32;
        cpa16(stg + ST_B + brow * B_STRIDE + bq * 32, wh);
        cpa16(stg + ST_B + brow * B_STRIDE + bq * 32 + 16, wh + 16);
        cp_commit();
    };

    float acc[4][2][4];
    #pragma unroll
    for (int mt = 0; mt < 4; mt++)
        #pragma unroll
        for (int nb = 0; nb < 2; nb++)
            #pragma unroll
            for (int r = 0; r < 4; r++) acc[mt][nb][r] = 0.0f;

    load_chunk(0, 0);

    for (int kc = 0; kc < 8; kc++) {
        if (kc < 7) load_chunk(kc + 1, (kc + 1) & 1);
        if (kc < 7) cp_wait1(); else cp_wait0();
        __syncthreads();

        uint32_t stg = sbase + OFF_STAGE + (kc & 1) * STAGE_SZ;

        #pragma unroll
        for (int ks = 0; ks < 4; ks++) {
            int k0 = ks * 16;
            uint32_t bf[2][2];
            int sel = lane >> 3;
            int rinm = lane & 7;
            {
                int n = wn * 16 + (sel >> 1) * 8 + rinm;
                uint32_t bptr = stg + ST_B + n * B_STRIDE + k0 * 2 + (sel & 1) * 16;
                ldmatrix4(bf[0][0], bf[0][1], bf[1][0], bf[1][1], bptr);
            }
            #pragma unroll
            for (int mt = 0; mt < 4; mt++) {
                int row = wm * 64 + mt * 16 + (lane & 15);
                uint32_t boff = SWZ((uint32_t)(row * 128 + k0 * 2 + (lane >> 4) * 16));
                uint32_t a0, a1, a2, a3;
                ldmatrix4(a0, a1, a2, a3, stg + ST_A + boff);
                #pragma unroll
                for (int nb = 0; nb < 2; nb++)
                    mma16816(acc[mt][nb][0], acc[mt][nb][1], acc[mt][nb][2], acc[mt][nb][3],
                             a0, a1, a2, a3, bf[nb][0], bf[nb][1]);
            }
        }
        __syncthreads();
    }

    float* gates = (float*)(sp + OFF_STAGE);
    #pragma unroll
    for (int mt = 0; mt < 4; mt++) {
        #pragma unroll
        for (int nb = 0; nb < 2; nb++) {
            int r0 = wm * 64 + mt * 16 + (lane >> 2);
            int c0 = wn * 16 + nb * 8 + ((lane & 3) << 1);
            gates[r0 * GST + c0]           = acc[mt][nb][0];
            gates[r0 * GST + c0 + 1]       = acc[mt][nb][1];
            gates[(r0 + 8) * GST + c0]     = acc[mt][nb][2];
            gates[(r0 + 8) * GST + c0 + 1] = acc[mt][nb][3];
        }
    }
    __syncthreads();

    int hl = tid & 15;
    int hid_g = by * 16 + hl;
    #pragma unroll 4
    for (int it = 0; it < 8; it++) {
        int m = (tid >> 4) + (it << 4);
        int node = base + m;
        float4 gt = *(const float4*)(gates + m * GST + hl * 4);
        float4 xt = *(const float4*)(g_xtabp + (size_t)sty[m] * G4 + by * 64 + hl * 4);
        float ig = gt.x + xt.x;
        float fg = gt.y + xt.y;
        float gg = gt.z + xt.z;
        float og = gt.w + xt.w;
        float co = g_Ccat[(size_t)node * H2 + hid_g];          // dense!
        float cn = sigm_fast(fg) * co + sigm_fast(ig) * tanh_fast(gg);
        float hn = sigm_fast(og) * tanh_fast(cn);
        out[(size_t)node * H2 + hid_g] = hn;
        if (by < 16) {                                          // hid_g < 256: feed parent
            int parent = (node - 1) >> 1;
            int poff = (node & 1) ? 0 : 256;
            g_Acat[(size_t)parent * H2 + poff + hid_g] = __float2half_rn(hn);
            g_Ccat[(size_t)parent * H2 + poff + hid_g] = cn;
        }
    }
}

// ---------------- persistent small-levels kernel: levels 8..0, grid barrier ----------------
__device__ __forceinline__ void grid_bar(int nCTA) {
    __syncthreads();
    if (threadIdx.x == 0) {
        __threadfence();
        unsigned gen = atomicOr(&g_bargen, 0u);
        unsigned arrived = atomicAdd(&g_barcnt, 1u);
        if (arrived == (unsigned)(nCTA - 1)) {
            atomicExch(&g_barcnt, 0u);
            __threadfence();
            atomicAdd(&g_bargen, 1u);
        } else {
            while (atomicOr(&g_bargen, 0u) == gen) { }
        }
    }
    __syncthreads();
}

__global__ __launch_bounds__(256, 1) void small_levels_kernel(
    const int* __restrict__ types, float* __restrict__ out) {
    __shared__ float hbuf[H2];
    __shared__ float sgates[G4];
    int t = threadIdx.x;
    int nCTA = gridDim.x;

    for (int d = 8; d >= 0; d--) {
        int n = 1 << d;
        int s = n - 1;
        for (int node = s + blockIdx.x; node < s + n; node += nCTA) {
            __syncthreads();
            // dense h load (512 fp16 -> fp32 smem)
            hbuf[t]       = __half2float(g_Acat[(size_t)node * H2 + t]);
            hbuf[t + 256] = __half2float(g_Acat[(size_t)node * H2 + t + 256]);
            __syncthreads();

            int ty = types[node];
            float acc[8];
            #pragma unroll
            for (int q = 0; q < 8; q++) acc[q] = g_xtabp[(size_t)ty * G4 + q * 256 + t];
            const float* wp = g_WhTp + t;
            #pragma unroll 4
            for (int k = 0; k < H2; k++) {
                float hk = hbuf[k];
                const float* wk = wp + (size_t)k * G4;
                #pragma unroll
                for (int q = 0; q < 8; q++)
                    acc[q] = fmaf(wk[q * 256], hk, acc[q]);
            }
            #pragma unroll
            for (int q = 0; q < 8; q++) sgates[q * 256 + t] = acc[q];
            __syncthreads();

            #pragma unroll
            for (int q = 0; q < 2; q++) {
                int hid = q * 256 + t;
                float ig = sgates[hid * 4 + 0];
                float fg = sgates[hid * 4 + 1];
                float gg = sgates[hid * 4 + 2];
                float og = sgates[hid * 4 + 3];
                float co = g_Ccat[(size_t)node * H2 + hid];
                float cn = sigm_fast(fg) * co + sigm_fast(ig) * tanh_fast(gg);
                float hn = sigm_fast(og) * tanh_fast(cn);
                out[(size_t)node * H2 + hid] = hn;
                if (q == 0 && node > 0) {
                    int parent = (node - 1) >> 1;
                    int poff = (node & 1) ? 0 : 256;
                    g_Acat[(size_t)parent * H2 + poff + hid] = __float2half_rn(hn);
                    g_Ccat[(size_t)parent * H2 + poff + hid] = cn;
                }
            }
        }
        if (d > 0) grid_bar(nCTA);
    }
}

extern "C" void kernel_launch(void* const* d_in, const int* in_sizes, int n_in,
                              void* d_out, int out_size) {
    const int* types  = (const int*)d_in[0];
    const float* emb  = (const float*)d_in[3];
    const float* W_ih = (const float*)d_in[4];
    const float* W_hh = (const float*)d_in[5];
    const float* b_ih = (const float*)d_in[6];
    const float* b_hh = (const float*)d_in[7];
    float* out = (float*)d_out;

    cudaFuncSetAttribute(tc_level_kernel, cudaFuncAttributeMaxDynamicSharedMemorySize, SMEM_DYN);

    // #1 xtab, #2 wprep, #3 leaf, #4 = tc13 (profiled)
    xtab_kernel<<<VOCAB, 256>>>(emb, W_ih, b_ih, b_hh);
    wprep_kernel<<<dim3(G4 / 32, H2 / 32), dim3(32, 8)>>>(W_hh);
    leaf_kernel<<<2048, 256>>>(types, out);

    for (int d = 13; d >= 9; d--) {
        int n = 1 << d;
        int s = n - 1;
        tc_level_kernel<<<dim3(n / 128, 32), 256, SMEM_DYN>>>(types, out, s);
    }
    small_levels_kernel<<<148, 256>>>(types, out);
}

// round 11
// speedup vs baseline: 1.7552x; 1.7552x over previous
#include <cuda_runtime.h>
#include <cuda_fp16.h>
#include <math.h>
#include <stdint.h>

#define N_NODES 32767
#define HDIM 256
#define H2 512
#define G4 2048
#define VOCAB 32
#define LEAF0 16383
#define NPAR 16384

// ---------------- device state / tables ----------------
__device__ __half g_Acat[(size_t)NPAR * H2];    // concat child-h per parent (fp16)
__device__ float  g_Ccat[(size_t)NPAR * H2];    // concat child-c per parent (fp32)
__device__ float  g_xtabp[VOCAB * G4];          // permuted jj = hid*4+g
__device__ __half g_Wh[G4 * H2];                // permuted rows [jj][k] fp16
__device__ float  g_ltab_h[VOCAB * H2];
__device__ float  g_ltab_c[VOCAB * HDIM];
__device__ __half g_ltab_h16[VOCAB * HDIM];
__device__ unsigned g_barcnt = 0;
__device__ unsigned g_bargen = 0;

__device__ __forceinline__ float tanh_fast(float x) {
    float y;
    asm("tanh.approx.f32 %0, %1;" : "=f"(y) : "f"(x));
    return y;
}
__device__ __forceinline__ float sigm_fast(float x) {
    return fmaf(0.5f, tanh_fast(0.5f * x), 0.5f);
}

__device__ __forceinline__ uint32_t smem_u32(const void* p) {
    uint32_t a;
    asm("{ .reg .u64 t; cvta.to.shared.u64 t, %1; cvt.u32.u64 %0, t; }" : "=r"(a) : "l"(p));
    return a;
}
__device__ __forceinline__ void cpa16(uint32_t dst, const void* src) {
    asm volatile("cp.async.cg.shared.global [%0], [%1], 16;" :: "r"(dst), "l"(src));
}
__device__ __forceinline__ void cp_commit() { asm volatile("cp.async.commit_group;"); }
__device__ __forceinline__ void cp_wait1() { asm volatile("cp.async.wait_group 1;"); }
__device__ __forceinline__ void cp_wait0() { asm volatile("cp.async.wait_group 0;"); }

__device__ __forceinline__ void ldmatrix4(uint32_t& r0, uint32_t& r1, uint32_t& r2, uint32_t& r3,
                                          uint32_t addr) {
    asm volatile("ldmatrix.sync.aligned.m8n8.x4.shared.b16 {%0,%1,%2,%3}, [%4];"
                 : "=r"(r0), "=r"(r1), "=r"(r2), "=r"(r3) : "r"(addr));
}
__device__ __forceinline__ void mma16816(float& d0, float& d1, float& d2, float& d3,
                                         uint32_t a0, uint32_t a1, uint32_t a2, uint32_t a3,
                                         uint32_t b0, uint32_t b1) {
    asm volatile(
        "mma.sync.aligned.m16n8k16.row.col.f32.f16.f16.f32 "
        "{%0,%1,%2,%3}, {%4,%5,%6,%7}, {%8,%9}, {%0,%1,%2,%3};"
        : "+f"(d0), "+f"(d1), "+f"(d2), "+f"(d3)
        : "r"(a0), "r"(a1), "r"(a2), "r"(a3), "r"(b0), "r"(b1));
}

#define SWZ(x) ((x) ^ (((x) >> 3) & 0x70))

// ---------------- tc smem layout ----------------
#define OFF_META   0
#define OFF_STAGE  2048
#define A_BYTES    16384
#define B_STRIDE   144
#define B_BYTES    (64 * B_STRIDE)
#define STAGE_SZ   (A_BYTES + B_BYTES)
#define ST_A       0
#define ST_B       A_BYTES
#define SMEM_DYN   (OFF_STAGE + 2 * STAGE_SZ)   // 53248 -> 4 CTAs/SM
#define GST        68

// ---------------- small persistent kernel smem ----------------
#define WS_STRIDE  261                          // uint32 per W row (522 fp16, bank-safe: 261%32=5)
#define SM_WS      0                            // 64 * 261 * 4 = 66816
#define SM_HBUF    66816                        // 512 * 4 = 2048
#define SM_SPART   68864                        // 4 * 64 * 4 = 1024
#define SM_SGATES  69888                        // 64 * 4 = 256
#define SMEM_SMALL 70144

// ---------------- prep: x table (permuted) + leaf tables ----------------
__global__ __launch_bounds__(256) void xtab_kernel(const float* __restrict__ emb,
                                                   const float* __restrict__ W_ih,
                                                   const float* __restrict__ b_ih,
                                                   const float* __restrict__ b_hh) {
    __shared__ float se[256];
    __shared__ float sx[G4];
    int v = blockIdx.x;
    int t = threadIdx.x;
    se[t] = emb[v * 256 + t];
    __syncthreads();
    #pragma unroll
    for (int m = 0; m < 8; m++) {
        int j = m * 256 + t;
        float acc = b_ih[j] + b_hh[j];
        const float4* wr = (const float4*)(W_ih + j * 256);
        #pragma unroll 8
        for (int k4 = 0; k4 < 64; k4++) {
            float4 w = wr[k4];
            acc += w.x * se[k4 * 4 + 0] + w.y * se[k4 * 4 + 1]
                 + w.z * se[k4 * 4 + 2] + w.w * se[k4 * 4 + 3];
        }
        g_xtabp[v * G4 + (j & 511) * 4 + (j >> 9)] = acc;
        sx[j] = acc;
    }
    __syncthreads();
    #pragma unroll
    for (int q = 0; q < 2; q++) {
        int hid = q * 256 + t;
        float ig = sx[hid];
        float gg = sx[1024 + hid];
        float og = sx[1536 + hid];
        float cn = sigm_fast(ig) * tanh_fast(gg);
        float hn = sigm_fast(og) * tanh_fast(cn);
        g_ltab_h[v * H2 + hid] = hn;
        if (q == 0) {
            g_ltab_c[v * HDIM + t] = cn;
            g_ltab_h16[v * HDIM + t] = __float2half_rn(hn);
        }
    }
}

// ---------------- prep: fp16 permuted rows ----------------
__global__ void wprep_kernel(const float* __restrict__ W_hh) {
    int j0 = blockIdx.x * 32;
    int k0 = blockIdx.y * 32;
    int tx = threadIdx.x, ty = threadIdx.y;
    #pragma unroll
    for (int r = 0; r < 32; r += 8) {
        int j = j0 + ty + r;
        float w = W_hh[j * H2 + k0 + tx];
        int jj = (j & 511) * 4 + (j >> 9);
        g_Wh[(size_t)jj * H2 + k0 + tx] = __float2half_rn(w);
    }
}

// ---------------- leaves: table copy, scatter into parent staging ----------------
__global__ __launch_bounds__(256) void leaf_kernel(const int* __restrict__ types,
                                                   float* __restrict__ out) {
    int wid = threadIdx.x >> 5;
    int lane = threadIdx.x & 31;
    int node = LEAF0 + blockIdx.x * 8 + wid;
    if (node >= N_NODES) return;
    int v = types[node];
    const float4* sh = (const float4*)(g_ltab_h + (size_t)v * H2);
    float4* dh = (float4*)(out + (size_t)node * H2);
    #pragma unroll
    for (int q = 0; q < 4; q++) dh[lane + 32 * q] = sh[lane + 32 * q];
    int parent = (node - 1) >> 1;
    int off = (node & 1) ? 0 : 256;
    const uint4* s16 = (const uint4*)(g_ltab_h16 + (size_t)v * HDIM);
    uint4* d16 = (uint4*)(g_Acat + (size_t)parent * H2 + off);
    d16[lane] = s16[lane];
    const float4* sc = (const float4*)(g_ltab_c + (size_t)v * HDIM);
    float4* dc = (float4*)(g_Ccat + (size_t)parent * H2 + off);
    #pragma unroll
    for (int q = 0; q < 2; q++) dc[lane + 32 * q] = sc[lane + 32 * q];
}

// ---------------- HMMA level kernel: M=128 x N=64 x K=512, dense A (levels 13..8) ----------------
__global__ __launch_bounds__(256, 4) void tc_level_kernel(
    const int* __restrict__ types, float* __restrict__ out, int s) {
    extern __shared__ char sp[];
    uint32_t sbase = smem_u32(sp);
    int tid = threadIdx.x;
    int lane = tid & 31;
    int wid = tid >> 5;
    int wm = wid >> 2;
    int wn = wid & 3;
    int by = blockIdx.y;
    int base = s + blockIdx.x * 128;

    int* sty = (int*)(sp + OFF_META);
    if (tid < 128) sty[tid] = types[base + tid];
    __syncthreads();

    int arow = tid >> 1, ahalf = tid & 1;
    int brow = tid >> 2, bq = tid & 3;

    auto load_chunk = [&](int kc, int st) {
        uint32_t stg = sbase + OFF_STAGE + st * STAGE_SZ;
        const char* ah = (const char*)(g_Acat + (size_t)(base + arow) * H2 + kc * 64) + ahalf * 64;
        #pragma unroll
        for (int q = 0; q < 4; q++) {
            uint32_t boff = arow * 128 + ahalf * 64 + q * 16;
            cpa16(stg + ST_A + SWZ(boff), ah + q * 16);
        }
        const char* wh = (const char*)(g_Wh + (size_t)(by * 64 + brow) * H2 + kc * 64) + bq * 32;
        cpa16(stg + ST_B + brow * B_STRIDE + bq * 32, wh);
        cpa16(stg + ST_B + brow * B_STRIDE + bq * 32 + 16, wh + 16);
        cp_commit();
    };

    float acc[4][2][4];
    #pragma unroll
    for (int mt = 0; mt < 4; mt++)
        #pragma unroll
        for (int nb = 0; nb < 2; nb++)
            #pragma unroll
            for (int r = 0; r < 4; r++) acc[mt][nb][r] = 0.0f;

    load_chunk(0, 0);

    for (int kc = 0; kc < 8; kc++) {
        if (kc < 7) load_chunk(kc + 1, (kc + 1) & 1);
        if (kc < 7) cp_wait1(); else cp_wait0();
        __syncthreads();

        uint32_t stg = sbase + OFF_STAGE + (kc & 1) * STAGE_SZ;

        #pragma unroll
        for (int ks = 0; ks < 4; ks++) {
            int k0 = ks * 16;
            uint32_t bf[2][2];
            int sel = lane >> 3;
            int rinm = lane & 7;
            {
                int n = wn * 16 + (sel >> 1) * 8 + rinm;
                uint32_t bptr = stg + ST_B + n * B_STRIDE + k0 * 2 + (sel & 1) * 16;
                ldmatrix4(bf[0][0], bf[0][1], bf[1][0], bf[1][1], bptr);
            }
            #pragma unroll
            for (int mt = 0; mt < 4; mt++) {
                int row = wm * 64 + mt * 16 + (lane & 15);
                uint32_t boff = SWZ((uint32_t)(row * 128 + k0 * 2 + (lane >> 4) * 16));
                uint32_t a0, a1, a2, a3;
                ldmatrix4(a0, a1, a2, a3, stg + ST_A + boff);
                #pragma unroll
                for (int nb = 0; nb < 2; nb++)
                    mma16816(acc[mt][nb][0], acc[mt][nb][1], acc[mt][nb][2], acc[mt][nb][3],
                             a0, a1, a2, a3, bf[nb][0], bf[nb][1]);
            }
        }
        __syncthreads();
    }

    float* gates = (float*)(sp + OFF_STAGE);
    #pragma unroll
    for (int mt = 0; mt < 4; mt++) {
        #pragma unroll
        for (int nb = 0; nb < 2; nb++) {
            int r0 = wm * 64 + mt * 16 + (lane >> 2);
            int c0 = wn * 16 + nb * 8 + ((lane & 3) << 1);
            gates[r0 * GST + c0]           = acc[mt][nb][0];
            gates[r0 * GST + c0 + 1]       = acc[mt][nb][1];
            gates[(r0 + 8) * GST + c0]     = acc[mt][nb][2];
            gates[(r0 + 8) * GST + c0 + 1] = acc[mt][nb][3];
        }
    }
    __syncthreads();

    int hl = tid & 15;
    int hid_g = by * 16 + hl;
    #pragma unroll 4
    for (int it = 0; it < 8; it++) {
        int m = (tid >> 4) + (it << 4);
        int node = base + m;
        float4 gt = *(const float4*)(gates + m * GST + hl * 4);
        float4 xt = *(const float4*)(g_xtabp + (size_t)sty[m] * G4 + by * 64 + hl * 4);
        float ig = gt.x + xt.x;
        float fg = gt.y + xt.y;
        float gg = gt.z + xt.z;
        float og = gt.w + xt.w;
        float co = g_Ccat[(size_t)node * H2 + hid_g];
        float cn = sigm_fast(fg) * co + sigm_fast(ig) * tanh_fast(gg);
        float hn = sigm_fast(og) * tanh_fast(cn);
        out[(size_t)node * H2 + hid_g] = hn;
        if (by < 16) {
            int parent = (node - 1) >> 1;
            int poff = (node & 1) ? 0 : 256;
            g_Acat[(size_t)parent * H2 + poff + hid_g] = __float2half_rn(hn);
            g_Ccat[(size_t)parent * H2 + poff + hid_g] = cn;
        }
    }
}

// ---------------- grid barrier ----------------
__device__ __forceinline__ void grid_bar(int nCTA) {
    __syncthreads();
    if (threadIdx.x == 0) {
        __threadfence();
        unsigned gen = atomicOr(&g_bargen, 0u);
        unsigned arrived = atomicAdd(&g_barcnt, 1u);
        if (arrived == (unsigned)(nCTA - 1)) {
            atomicExch(&g_barcnt, 0u);
            __threadfence();
            atomicAdd(&g_bargen, 1u);
        } else {
            while (atomicOr(&g_bargen, 0u) == gen) { }
        }
    }
    __syncthreads();
}

// ---------------- persistent small-levels kernel: levels 7..0 ----------------
// 128 CTAs = 4 node-groups x 32 jj-slices. Each CTA keeps its 64-row W slice
// (jj in [slice*64, slice*64+64), padded stride 522 fp16) resident in smem.
__global__ __launch_bounds__(256, 1) void small_levels_kernel(
    const int* __restrict__ types, float* __restrict__ out) {
    extern __shared__ char sm[];
    uint32_t* ws = (uint32_t*)(sm + SM_WS);
    float* hbuf = (float*)(sm + SM_HBUF);
    float* spart = (float*)(sm + SM_SPART);
    float* sgates = (float*)(sm + SM_SGATES);
    int t = threadIdx.x;
    int slice = blockIdx.x & 31;
    int grp = blockIdx.x >> 5;     // 0..3

    // load W slice once (64 rows x 256 uint32)
    {
        const uint32_t* src = (const uint32_t*)(g_Wh + (size_t)slice * 64 * H2);
        #pragma unroll
        for (int i = t; i < 64 * 256; i += 256) {
            int row = i >> 8, q = i & 255;
            ws[row * WS_STRIDE + q] = src[row * 256 + q];
        }
    }
    __syncthreads();

    int jj = t & 63;               // local gate row
    int kq = t >> 6;               // k quarter (uniform per warp pair)

    for (int d = 7; d >= 0; d--) {
        int n = 1 << d, s = n - 1;
        for (int node = s + grp; node < s + n; node += 4) {
            __syncthreads();
            hbuf[t]       = __half2float(g_Acat[(size_t)node * H2 + t]);
            hbuf[t + 256] = __half2float(g_Acat[(size_t)node * H2 + t + 256]);
            __syncthreads();

            float acc = 0.0f;
            const uint32_t* wrow = ws + jj * WS_STRIDE + kq * 64;
            const float* hrow = hbuf + kq * 128;
            #pragma unroll 8
            for (int kk = 0; kk < 64; kk++) {
                __half2 w2 = *(const __half2*)&wrow[kk];
                float2 wf = __half22float2(w2);
                float2 h2 = *(const float2*)&hrow[kk * 2];
                acc = fmaf(wf.x, h2.x, acc);
                acc = fmaf(wf.y, h2.y, acc);
            }
            spart[t] = acc;        // spart[kq*64 + jj]
            __syncthreads();
            if (t < 64) {
                int ty = types[node];
                sgates[t] = spart[t] + spart[64 + t] + spart[128 + t] + spart[192 + t]
                          + g_xtabp[(size_t)ty * G4 + slice * 64 + t];
            }
            __syncthreads();
            if (t < 16) {
                int hid_g = slice * 16 + t;
                float ig = sgates[t * 4 + 0];
                float fg = sgates[t * 4 + 1];
                float gg = sgates[t * 4 + 2];
                float og = sgates[t * 4 + 3];
                float co = g_Ccat[(size_t)node * H2 + hid_g];
                float cn = sigm_fast(fg) * co + sigm_fast(ig) * tanh_fast(gg);
                float hn = sigm_fast(og) * tanh_fast(cn);
                out[(size_t)node * H2 + hid_g] = hn;
                if (hid_g < HDIM && node > 0) {
                    int parent = (node - 1) >> 1;
                    int poff = (node & 1) ? 0 : 256;
                    g_Acat[(size_t)parent * H2 + poff + hid_g] = __float2half_rn(hn);
                    g_Ccat[(size_t)parent * H2 + poff + hid_g] = cn;
                }
            }
        }
        if (d > 0) grid_bar(gridDim.x);
    }
}

extern "C" void kernel_launch(void* const* d_in, const int* in_sizes, int n_in,
                              void* d_out, int out_size) {
    const int* types  = (const int*)d_in[0];
    const float* emb  = (const float*)d_in[3];
    const float* W_ih = (const float*)d_in[4];
    const float* W_hh = (const float*)d_in[5];
    const float* b_ih = (const float*)d_in[6];
    const float* b_hh = (const float*)d_in[7];
    float* out = (float*)d_out;

    cudaFuncSetAttribute(tc_level_kernel, cudaFuncAttributeMaxDynamicSharedMemorySize, SMEM_DYN);
    cudaFuncSetAttribute(small_levels_kernel, cudaFuncAttributeMaxDynamicSharedMemorySize, SMEM_SMALL);

    // #1 xtab, #2 wprep, #3 leaf, #4 = tc13 (profiled)
    xtab_kernel<<<VOCAB, 256>>>(emb, W_ih, b_ih, b_hh);
    wprep_kernel<<<dim3(G4 / 32, H2 / 32), dim3(32, 8)>>>(W_hh);
    leaf_kernel<<<2048, 256>>>(types, out);

    for (int d = 13; d >= 8; d--) {
        int n = 1 << d;
        int s = n - 1;
        tc_level_kernel<<<dim3(n / 128, 32), 256, SMEM_DYN>>>(types, out, s);
    }
    small_levels_kernel<<<128, 256, SMEM_SMALL>>>(types, out);
}

// round 13
// speedup vs baseline: 2.0247x; 1.1535x over previous
#include <cuda_runtime.h>
#include <cuda_fp16.h>
#include <math.h>
#include <stdint.h>

#define N_NODES 32767
#define HDIM 256
#define H2 512
#define G4 2048
#define VOCAB 32
#define LEAF0 16383
#define NPAR 16384

// ---------------- device state / tables ----------------
__device__ __half g_Acat[(size_t)NPAR * H2];    // concat child-h per parent (fp16)
__device__ float  g_Ccat[(size_t)NPAR * H2];    // concat child-c per parent (fp32)
__device__ float  g_xtabp[VOCAB * G4];          // permuted jj = hid*4+g
__device__ __half g_Wh[G4 * H2];                // permuted rows [jj][k] fp16
__device__ float  g_ltab_h[VOCAB * H2];
__device__ float  g_ltab_c[VOCAB * HDIM];
__device__ __half g_ltab_h16[VOCAB * HDIM];
__device__ unsigned g_barcnt = 0;
__device__ unsigned g_bargen = 0;

__device__ __forceinline__ float tanh_fast(float x) {
    float y;
    asm("tanh.approx.f32 %0, %1;" : "=f"(y) : "f"(x));
    return y;
}
__device__ __forceinline__ float sigm_fast(float x) {
    return fmaf(0.5f, tanh_fast(0.5f * x), 0.5f);
}

__device__ __forceinline__ uint32_t smem_u32(const void* p) {
    uint32_t a;
    asm("{ .reg .u64 t; cvta.to.shared.u64 t, %1; cvt.u32.u64 %0, t; }" : "=r"(a) : "l"(p));
    return a;
}
__device__ __forceinline__ void cpa16(uint32_t dst, const void* src) {
    asm volatile("cp.async.cg.shared.global [%0], [%1], 16;" :: "r"(dst), "l"(src));
}
__device__ __forceinline__ void cp_commit() { asm volatile("cp.async.commit_group;"); }
__device__ __forceinline__ void cp_wait2() { asm volatile("cp.async.wait_group 2;"); }
__device__ __forceinline__ void cp_wait1() { asm volatile("cp.async.wait_group 1;"); }
__device__ __forceinline__ void cp_wait0() { asm volatile("cp.async.wait_group 0;"); }

__device__ __forceinline__ void ldmatrix4(uint32_t& r0, uint32_t& r1, uint32_t& r2, uint32_t& r3,
                                          uint32_t addr) {
    asm volatile("ldmatrix.sync.aligned.m8n8.x4.shared.b16 {%0,%1,%2,%3}, [%4];"
                 : "=r"(r0), "=r"(r1), "=r"(r2), "=r"(r3) : "r"(addr));
}
__device__ __forceinline__ void mma16816(float& d0, float& d1, float& d2, float& d3,
                                         uint32_t a0, uint32_t a1, uint32_t a2, uint32_t a3,
                                         uint32_t b0, uint32_t b1) {
    asm volatile(
        "mma.sync.aligned.m16n8k16.row.col.f32.f16.f16.f32 "
        "{%0,%1,%2,%3}, {%4,%5,%6,%7}, {%8,%9}, {%0,%1,%2,%3};"
        : "+f"(d0), "+f"(d1), "+f"(d2), "+f"(d3)
        : "r"(a0), "r"(a1), "r"(a2), "r"(a3), "r"(b0), "r"(b1));
}

// SW64 swizzle for 64B rows
#define SWZ64(x) ((x) ^ (((x) >> 3) & 0x30))

// ---------------- tc smem layout (Kc=32, 4 stages) ----------------
#define OFF_META   0
#define OFF_STAGE  2048
#define A_BYTES    8192                  // 128 rows x 64B (SW64)
#define B_STRIDE   80                    // 40 fp16 per row (32 data + 8 pad)
#define B_BYTES    (64 * B_STRIDE)       // 5120
#define STAGE_SZ   (A_BYTES + B_BYTES)   // 13312
#define ST_A       0
#define ST_B       A_BYTES
#define N_STAGE    4
#define SMEM_DYN   (OFF_STAGE + N_STAGE * STAGE_SZ)   // 55296 -> 4 CTAs/SM
#define GST        68

// ---------------- small persistent kernel smem ----------------
#define NGRP       8
#define WS_STRIDE  261                   // uint32 per W row (bank-safe)
#define SM_WS      0                     // 64*261*4 = 66816
#define SM_HB      66816                 // 2 x 1024 (512 fp16 each)
#define SM_CB      68864                 // 2 x 64   (16 fp32 each)
#define SM_XB      68992                 // 2 x 256  (64 fp32 each)
#define SM_SPART   69504                 // 256 fp32
#define SM_SGATES  70528                 // 64 fp32
#define SMEM_SMALL 70784                 // x2 CTAs/SM = 141.6 KB, fits

// ---------------- prep: x table (permuted) + leaf tables ----------------
__global__ __launch_bounds__(256) void xtab_kernel(const float* __restrict__ emb,
                                                   const float* __restrict__ W_ih,
                                                   const float* __restrict__ b_ih,
                                                   const float* __restrict__ b_hh) {
    __shared__ float se[256];
    __shared__ float sx[G4];
    int v = blockIdx.x;
    int t = threadIdx.x;
    se[t] = emb[v * 256 + t];
    __syncthreads();
    #pragma unroll
    for (int m = 0; m < 8; m++) {
        int j = m * 256 + t;
        float acc = b_ih[j] + b_hh[j];
        const float4* wr = (const float4*)(W_ih + j * 256);
        #pragma unroll 8
        for (int k4 = 0; k4 < 64; k4++) {
            float4 w = wr[k4];
            acc += w.x * se[k4 * 4 + 0] + w.y * se[k4 * 4 + 1]
                 + w.z * se[k4 * 4 + 2] + w.w * se[k4 * 4 + 3];
        }
        g_xtabp[v * G4 + (j & 511) * 4 + (j >> 9)] = acc;
        sx[j] = acc;
    }
    __syncthreads();
    #pragma unroll
    for (int q = 0; q < 2; q++) {
        int hid = q * 256 + t;
        float ig = sx[hid];
        float gg = sx[1024 + hid];
        float og = sx[1536 + hid];
        float cn = sigm_fast(ig) * tanh_fast(gg);
        float hn = sigm_fast(og) * tanh_fast(cn);
        g_ltab_h[v * H2 + hid] = hn;
        if (q == 0) {
            g_ltab_c[v * HDIM + t] = cn;
            g_ltab_h16[v * HDIM + t] = __float2half_rn(hn);
        }
    }
}

// ---------------- prep: fp16 permuted rows ----------------
__global__ void wprep_kernel(const float* __restrict__ W_hh) {
    int j0 = blockIdx.x * 32;
    int k0 = blockIdx.y * 32;
    int tx = threadIdx.x, ty = threadIdx.y;
    #pragma unroll
    for (int r = 0; r < 32; r += 8) {
        int j = j0 + ty + r;
        float w = W_hh[j * H2 + k0 + tx];
        int jj = (j & 511) * 4 + (j >> 9);
        g_Wh[(size_t)jj * H2 + k0 + tx] = __float2half_rn(w);
    }
}

// ---------------- leaves: table copy, scatter into parent staging ----------------
__global__ __launch_bounds__(256) void leaf_kernel(const int* __restrict__ types,
                                                   float* __restrict__ out) {
    int wid = threadIdx.x >> 5;
    int lane = threadIdx.x & 31;
    int node = LEAF0 + blockIdx.x * 8 + wid;
    if (node >= N_NODES) return;
    int v = types[node];
    const float4* sh = (const float4*)(g_ltab_h + (size_t)v * H2);
    float4* dh = (float4*)(out + (size_t)node * H2);
    #pragma unroll
    for (int q = 0; q < 4; q++) dh[lane + 32 * q] = sh[lane + 32 * q];
    int parent = (node - 1) >> 1;
    int off = (node & 1) ? 0 : 256;
    const uint4* s16 = (const uint4*)(g_ltab_h16 + (size_t)v * HDIM);
    uint4* d16 = (uint4*)(g_Acat + (size_t)parent * H2 + off);
    d16[lane] = s16[lane];
    const float4* sc = (const float4*)(g_ltab_c + (size_t)v * HDIM);
    float4* dc = (float4*)(g_Ccat + (size_t)parent * H2 + off);
    #pragma unroll
    for (int q = 0; q < 2; q++) dc[lane + 32 * q] = sc[lane + 32 * q];
}

// ---------------- HMMA level kernel: M=128 x N=64, Kc=32, 4-stage (levels 13..8) ----------------
__global__ __launch_bounds__(256, 4) void tc_level_kernel(
    const int* __restrict__ types, float* __restrict__ out, int s) {
    extern __shared__ char sp[];
    uint32_t sbase = smem_u32(sp);
    int tid = threadIdx.x;
    int lane = tid & 31;
    int wid = tid >> 5;
    int wm = wid >> 2;
    int wn = wid & 3;
    int by = blockIdx.y;
    int base = s + blockIdx.x * 128;

    int* sty = (int*)(sp + OFF_META);
    if (tid < 128) sty[tid] = types[base + tid];

    int arow = tid >> 1, ahalf = tid & 1;
    int brow = tid >> 2, bq = tid & 3;

    auto load_chunk = [&](int kc, int st) {
        uint32_t stg = sbase + OFF_STAGE + st * STAGE_SZ;
        const char* ah = (const char*)(g_Acat + (size_t)(base + arow) * H2 + kc * 32) + ahalf * 32;
        uint32_t boff = arow * 64 + ahalf * 32;
        cpa16(stg + ST_A + SWZ64(boff), ah);
        cpa16(stg + ST_A + SWZ64(boff + 16), ah + 16);
        const char* wh = (const char*)(g_Wh + (size_t)(by * 64 + brow) * H2 + kc * 32) + bq * 16;
        cpa16(stg + ST_B + brow * B_STRIDE + bq * 16, wh);
        cp_commit();
    };

    float acc[4][2][4];
    #pragma unroll
    for (int mt = 0; mt < 4; mt++)
        #pragma unroll
        for (int nb = 0; nb < 2; nb++)
            #pragma unroll
            for (int r = 0; r < 4; r++) acc[mt][nb][r] = 0.0f;

    load_chunk(0, 0);
    load_chunk(1, 1);
    load_chunk(2, 2);

    for (int kc = 0; kc < 16; kc++) {
        if (kc < 14) cp_wait2(); else if (kc == 14) cp_wait1(); else cp_wait0();
        __syncthreads();
        if (kc < 13) load_chunk(kc + 3, (kc + 3) & 3);

        uint32_t stg = sbase + OFF_STAGE + (kc & 3) * STAGE_SZ;
        #pragma unroll
        for (int ks = 0; ks < 2; ks++) {
            int k0 = ks * 16;
            uint32_t bf[2][2];
            int sel = lane >> 3;
            int rinm = lane & 7;
            {
                int n = wn * 16 + (sel >> 1) * 8 + rinm;
                uint32_t bptr = stg + ST_B + n * B_STRIDE + k0 * 2 + (sel & 1) * 16;
                ldmatrix4(bf[0][0], bf[0][1], bf[1][0], bf[1][1], bptr);
            }
            #pragma unroll
            for (int mt = 0; mt < 4; mt++) {
                int row = wm * 64 + mt * 16 + (lane & 15);
                uint32_t boff = SWZ64((uint32_t)(row * 64 + k0 * 2 + (lane >> 4) * 16));
                uint32_t a0, a1, a2, a3;
                ldmatrix4(a0, a1, a2, a3, stg + ST_A + boff);
                #pragma unroll
                for (int nb = 0; nb < 2; nb++)
                    mma16816(acc[mt][nb][0], acc[mt][nb][1], acc[mt][nb][2], acc[mt][nb][3],
                             a0, a1, a2, a3, bf[nb][0], bf[nb][1]);
            }
        }
    }
    __syncthreads();

    float* gates = (float*)(sp + OFF_STAGE);
    #pragma unroll
    for (int mt = 0; mt < 4; mt++) {
        #pragma unroll
        for (int nb = 0; nb < 2; nb++) {
            int r0 = wm * 64 + mt * 16 + (lane >> 2);
            int c0 = wn * 16 + nb * 8 + ((lane & 3) << 1);
            gates[r0 * GST + c0]           = acc[mt][nb][0];
            gates[r0 * GST + c0 + 1]       = acc[mt][nb][1];
            gates[(r0 + 8) * GST + c0]     = acc[mt][nb][2];
            gates[(r0 + 8) * GST + c0 + 1] = acc[mt][nb][3];
        }
    }
    __syncthreads();

    int hl = tid & 15;
    int hid_g = by * 16 + hl;
    #pragma unroll 4
    for (int it = 0; it < 8; it++) {
        int m = (tid >> 4) + (it << 4);
        int node = base + m;
        float4 gt = *(const float4*)(gates + m * GST + hl * 4);
        float4 xt = *(const float4*)(g_xtabp + (size_t)sty[m] * G4 + by * 64 + hl * 4);
        float ig = gt.x + xt.x;
        float fg = gt.y + xt.y;
        float gg = gt.z + xt.z;
        float og = gt.w + xt.w;
        float co = g_Ccat[(size_t)node * H2 + hid_g];
        float cn = sigm_fast(fg) * co + sigm_fast(ig) * tanh_fast(gg);
        float hn = sigm_fast(og) * tanh_fast(cn);
        out[(size_t)node * H2 + hid_g] = hn;
        if (by < 16) {
            int parent = (node - 1) >> 1;
            int poff = (node & 1) ? 0 : 256;
            g_Acat[(size_t)parent * H2 + poff + hid_g] = __float2half_rn(hn);
            g_Ccat[(size_t)parent * H2 + poff + hid_g] = cn;
        }
    }
}

// ---------------- grid barrier ----------------
__device__ __forceinline__ void grid_bar(int nCTA) {
    __syncthreads();
    if (threadIdx.x == 0) {
        __threadfence();
        unsigned gen = atomicOr(&g_bargen, 0u);
        unsigned arrived = atomicAdd(&g_barcnt, 1u);
        if (arrived == (unsigned)(nCTA - 1)) {
            atomicExch(&g_barcnt, 0u);
            __threadfence();
            atomicAdd(&g_bargen, 1u);
        } else {
            while (atomicOr(&g_bargen, 0u) == gen) { }
        }
    }
    __syncthreads();
}

// ---------------- persistent small-levels kernel: levels 7..0 ----------------
// 256 CTAs = 8 node-groups x 32 jj-slices. __launch_bounds__(256, 2) caps regs
// at 128/thread -> 2 CTAs/SM guaranteed -> 296 slots >= 256 CTAs co-resident.
__global__ __launch_bounds__(256, 2) void small_levels_kernel(
    const int* __restrict__ types, float* __restrict__ out) {
    extern __shared__ char sm[];
    uint32_t sb = smem_u32(sm);
    uint32_t* ws = (uint32_t*)(sm + SM_WS);
    float* spart = (float*)(sm + SM_SPART);
    float* sgates = (float*)(sm + SM_SGATES);
    int t = threadIdx.x;
    int slice = blockIdx.x & 31;
    int grp = blockIdx.x >> 5;     // 0..7

    // load W slice once (64 rows x 256 uint32)
    {
        const uint32_t* src = (const uint32_t*)(g_Wh + (size_t)slice * 64 * H2);
        #pragma unroll
        for (int i = t; i < 64 * 256; i += 256) {
            int row = i >> 8, q = i & 255;
            ws[row * WS_STRIDE + q] = src[row * 256 + q];
        }
    }
    __syncthreads();

    int jj = t & 63;
    int kq = t >> 6;

    auto issue_node = [&](int nd, int buf) {
        if (t < 64) {
            cpa16(sb + SM_HB + buf * 1024 + t * 16,
                  (const char*)(g_Acat + (size_t)nd * H2) + t * 16);
        } else if (t < 68) {
            int q = t - 64;
            cpa16(sb + SM_CB + buf * 64 + q * 16,
                  (const char*)(g_Ccat + (size_t)nd * H2 + slice * 16) + q * 16);
        } else if (t < 84) {
            int q = t - 68;
            int tyn = types[nd];
            cpa16(sb + SM_XB + buf * 256 + q * 16,
                  (const char*)(g_xtabp + (size_t)tyn * G4 + slice * 64) + q * 16);
        }
        cp_commit();
    };

    for (int d = 7; d >= 0; d--) {
        int n = 1 << d, s = n - 1;
        int node0 = s + grp;
        int cur = 0;
        if (node0 < s + n) issue_node(node0, 0);
        for (int node = node0; node < s + n; node += NGRP) {
            cp_wait0();
            __syncthreads();
            if (node + NGRP < s + n) issue_node(node + NGRP, cur ^ 1);

            const uint32_t* wrow = ws + jj * WS_STRIDE + kq * 64;
            const uint32_t* hrow = (const uint32_t*)(sm + SM_HB + cur * 1024) + kq * 64;
            float acc = 0.0f;
            #pragma unroll 8
            for (int kk = 0; kk < 64; kk++) {
                float2 wf = __half22float2(*(const __half2*)&wrow[kk]);
                float2 hf = __half22float2(*(const __half2*)&hrow[kk]);
                acc = fmaf(wf.x, hf.x, acc);
                acc = fmaf(wf.y, hf.y, acc);
            }
            spart[t] = acc;
            __syncthreads();
            if (t < 64) {
                const float* xb = (const float*)(sm + SM_XB + cur * 256);
                sgates[t] = spart[t] + spart[64 + t] + spart[128 + t] + spart[192 + t] + xb[t];
            }
            __syncthreads();
            if (t < 16) {
                int hid_g = slice * 16 + t;
                const float* cb = (const float*)(sm + SM_CB + cur * 64);
                float ig = sgates[t * 4 + 0];
                float fg = sgates[t * 4 + 1];
                float gg = sgates[t * 4 + 2];
                float og = sgates[t * 4 + 3];
                float co = cb[t];
                float cn = sigm_fast(fg) * co + sigm_fast(ig) * tanh_fast(gg);
                float hn = sigm_fast(og) * tanh_fast(cn);
                out[(size_t)node * H2 + hid_g] = hn;
                if (hid_g < HDIM && node > 0) {
                    int parent = (node - 1) >> 1;
                    int poff = (node & 1) ? 0 : 256;
                    g_Acat[(size_t)parent * H2 + poff + hid_g] = __float2half_rn(hn);
                    g_Ccat[(size_t)parent * H2 + poff + hid_g] = cn;
                }
            }
            cur ^= 1;
        }
        if (d > 0) grid_bar(gridDim.x);
    }
}

extern "C" void kernel_launch(void* const* d_in, const int* in_sizes, int n_in,
                              void* d_out, int out_size) {
    const int* types  = (const int*)d_in[0];
    const float* emb  = (const float*)d_in[3];
    const float* W_ih = (const float*)d_in[4];
    const float* W_hh = (const float*)d_in[5];
    const float* b_ih = (const float*)d_in[6];
    const float* b_hh = (const float*)d_in[7];
    float* out = (float*)d_out;

    cudaFuncSetAttribute(tc_level_kernel, cudaFuncAttributeMaxDynamicSharedMemorySize, SMEM_DYN);
    cudaFuncSetAttribute(small_levels_kernel, cudaFuncAttributeMaxDynamicSharedMemorySize, SMEM_SMALL);

    // #1 xtab, #2 wprep, #3 leaf, #4 = tc13 (profiled)
    xtab_kernel<<<VOCAB, 256>>>(emb, W_ih, b_ih, b_hh);
    wprep_kernel<<<dim3(G4 / 32, H2 / 32), dim3(32, 8)>>>(W_hh);
    leaf_kernel<<<2048, 256>>>(types, out);

    for (int d = 13; d >= 8; d--) {
        int n = 1 << d;
        int s = n - 1;
        tc_level_kernel<<<dim3(n / 128, 32), 256, SMEM_DYN>>>(types, out, s);
    }
    small_levels_kernel<<<256, 256, SMEM_SMALL>>>(types, out);
}

// round 16
// speedup vs baseline: 2.1802x; 1.0768x over previous
#include <cuda_runtime.h>
#include <cuda_fp16.h>
#include <math.h>
#include <stdint.h>

#define N_NODES 32767
#define HDIM 256
#define H2 512
#define G4 2048
#define VOCAB 32
#define LEAF0 16383
#define NPAR 16384

// ---------------- device state / tables ----------------
__device__ __half g_Acat[(size_t)NPAR * H2];    // concat child-h per parent (fp16)
__device__ float  g_Ccat[(size_t)NPAR * H2];    // concat child-c per parent (fp32)
__device__ float  g_xtabp[VOCAB * G4];          // permuted jj = hid*4+g
__device__ __half g_Wh[G4 * H2];                // permuted rows [jj][k] fp16
__device__ float  g_ltab_h[VOCAB * H2];
__device__ float  g_ltab_c[VOCAB * HDIM];
__device__ __half g_ltab_h16[VOCAB * HDIM];
__device__ unsigned g_barcnt = 0;
__device__ unsigned g_bargen = 0;

__device__ __forceinline__ float tanh_fast(float x) {
    float y;
    asm("tanh.approx.f32 %0, %1;" : "=f"(y) : "f"(x));
    return y;
}
__device__ __forceinline__ float sigm_fast(float x) {
    return fmaf(0.5f, tanh_fast(0.5f * x), 0.5f);
}

__device__ __forceinline__ uint32_t smem_u32(const void* p) {
    uint32_t a;
    asm("{ .reg .u64 t; cvta.to.shared.u64 t, %1; cvt.u32.u64 %0, t; }" : "=r"(a) : "l"(p));
    return a;
}
__device__ __forceinline__ void cpa16(uint32_t dst, const void* src) {
    asm volatile("cp.async.cg.shared.global [%0], [%1], 16;" :: "r"(dst), "l"(src));
}
__device__ __forceinline__ void cp_commit() { asm volatile("cp.async.commit_group;"); }
__device__ __forceinline__ void cp_wait2() { asm volatile("cp.async.wait_group 2;"); }
__device__ __forceinline__ void cp_wait1() { asm volatile("cp.async.wait_group 1;"); }
__device__ __forceinline__ void cp_wait0() { asm volatile("cp.async.wait_group 0;"); }

__device__ __forceinline__ void ldmatrix4(uint32_t& r0, uint32_t& r1, uint32_t& r2, uint32_t& r3,
                                          uint32_t addr) {
    asm volatile("ldmatrix.sync.aligned.m8n8.x4.shared.b16 {%0,%1,%2,%3}, [%4];"
                 : "=r"(r0), "=r"(r1), "=r"(r2), "=r"(r3) : "r"(addr));
}
__device__ __forceinline__ void mma16816(float& d0, float& d1, float& d2, float& d3,
                                         uint32_t a0, uint32_t a1, uint32_t a2, uint32_t a3,
                                         uint32_t b0, uint32_t b1) {
    asm volatile(
        "mma.sync.aligned.m16n8k16.row.col.f32.f16.f16.f32 "
        "{%0,%1,%2,%3}, {%4,%5,%6,%7}, {%8,%9}, {%0,%1,%2,%3};"
        : "+f"(d0), "+f"(d1), "+f"(d2), "+f"(d3)
        : "r"(a0), "r"(a1), "r"(a2), "r"(a3), "r"(b0), "r"(b1));
}

// SW64 swizzle for 64B rows
#define SWZ64(x) ((x) ^ (((x) >> 3) & 0x30))

// ---------------- tc smem layout (Kc=32, 4 stages) ----------------
#define OFF_META   0
#define OFF_STAGE  2048
#define A_BYTES    8192                  // 128 rows x 64B (SW64)
#define B_STRIDE   80                    // 40 fp16 per row (32 data + 8 pad)
#define B_BYTES    (64 * B_STRIDE)       // 5120
#define STAGE_SZ   (A_BYTES + B_BYTES)   // 13312
#define ST_A       0
#define ST_B       A_BYTES
#define N_STAGE    4
#define SMEM_DYN   (OFF_STAGE + N_STAGE * STAGE_SZ)   // 55296 -> 4 CTAs/SM
#define GST        68

// ---------------- small persistent kernel smem ----------------
#define NGRP       8
#define WS_STRIDE  261                   // uint32 per W row (bank-safe)
#define SM_WS      0                     // 64*261*4 = 66816
#define SM_HB      66816                 // 2 x 1024 (512 fp16 each)
#define SM_CB      68864                 // 2 x 64   (16 fp32 each)
#define SM_XB      68992                 // 2 x 256  (64 fp32 each)
#define SM_SPART   69504                 // 256 fp32
#define SM_SGATES  70528                 // 64 fp32
#define SMEM_SMALL 70784                 // x2 CTAs/SM = 141.6 KB, fits

// ---------------- prep: x table (permuted) + leaf tables ----------------
__global__ __launch_bounds__(256) void xtab_kernel(const float* __restrict__ emb,
                                                   const float* __restrict__ W_ih,
                                                   const float* __restrict__ b_ih,
                                                   const float* __restrict__ b_hh) {
    __shared__ float se[256];
    __shared__ float sx[G4];
    int v = blockIdx.x;
    int t = threadIdx.x;
    se[t] = emb[v * 256 + t];
    __syncthreads();
    #pragma unroll
    for (int m = 0; m < 8; m++) {
        int j = m * 256 + t;
        float acc = b_ih[j] + b_hh[j];
        const float4* wr = (const float4*)(W_ih + j * 256);
        #pragma unroll 8
        for (int k4 = 0; k4 < 64; k4++) {
            float4 w = wr[k4];
            acc += w.x * se[k4 * 4 + 0] + w.y * se[k4 * 4 + 1]
                 + w.z * se[k4 * 4 + 2] + w.w * se[k4 * 4 + 3];
        }
        g_xtabp[v * G4 + (j & 511) * 4 + (j >> 9)] = acc;
        sx[j] = acc;
    }
    __syncthreads();
    #pragma unroll
    for (int q = 0; q < 2; q++) {
        int hid = q * 256 + t;
        float ig = sx[hid];
        float gg = sx[1024 + hid];
        float og = sx[1536 + hid];
        float cn = sigm_fast(ig) * tanh_fast(gg);
        float hn = sigm_fast(og) * tanh_fast(cn);
        g_ltab_h[v * H2 + hid] = hn;
        if (q == 0) {
            g_ltab_c[v * HDIM + t] = cn;
            g_ltab_h16[v * HDIM + t] = __float2half_rn(hn);
        }
    }
}

// ---------------- prep: fp16 permuted rows ----------------
__global__ void wprep_kernel(const float* __restrict__ W_hh) {
    int j0 = blockIdx.x * 32;
    int k0 = blockIdx.y * 32;
    int tx = threadIdx.x, ty = threadIdx.y;
    #pragma unroll
    for (int r = 0; r < 32; r += 8) {
        int j = j0 + ty + r;
        float w = W_hh[j * H2 + k0 + tx];
        int jj = (j & 511) * 4 + (j >> 9);
        g_Wh[(size_t)jj * H2 + k0 + tx] = __float2half_rn(w);
    }
}

// ---------------- leaves: table copy, scatter into parent staging ----------------
__global__ __launch_bounds__(256) void leaf_kernel(const int* __restrict__ types,
                                                   float* __restrict__ out) {
    int wid = threadIdx.x >> 5;
    int lane = threadIdx.x & 31;
    int node = LEAF0 + blockIdx.x * 8 + wid;
    if (node >= N_NODES) return;
    int v = types[node];
    const float4* sh = (const float4*)(g_ltab_h + (size_t)v * H2);
    float4* dh = (float4*)(out + (size_t)node * H2);
    #pragma unroll
    for (int q = 0; q < 4; q++) dh[lane + 32 * q] = sh[lane + 32 * q];
    int parent = (node - 1) >> 1;
    int off = (node & 1) ? 0 : 256;
    const uint4* s16 = (const uint4*)(g_ltab_h16 + (size_t)v * HDIM);
    uint4* d16 = (uint4*)(g_Acat + (size_t)parent * H2 + off);
    d16[lane] = s16[lane];
    const float4* sc = (const float4*)(g_ltab_c + (size_t)v * HDIM);
    float4* dc = (float4*)(g_Ccat + (size_t)parent * H2 + off);
    #pragma unroll
    for (int q = 0; q < 2; q++) dc[lane + 32 * q] = sc[lane + 32 * q];
}

// ---------------- HMMA level kernel: M=128 x N=64, Kc=32, 4-stage (levels 13..7) ----------------
// Warp tiling 4 wm x 2 wn (32M x 32N per warp): A smem reads x2, B reads x4
// (was A x4, B x2) -> 14% less smem read traffic since A tile > B tile.
__global__ __launch_bounds__(256, 4) void tc_level_kernel(
    const int* __restrict__ types, float* __restrict__ out, int s) {
    extern __shared__ char sp[];
    uint32_t sbase = smem_u32(sp);
    int tid = threadIdx.x;
    int lane = tid & 31;
    int wid = tid >> 5;
    int wm = wid >> 1;            // 0..3 (32 M-rows each)
    int wn = wid & 1;             // 0..1 (32 N-cols each)
    int by = blockIdx.y;
    int base = s + blockIdx.x * 128;

    int* sty = (int*)(sp + OFF_META);
    if (tid < 128) sty[tid] = types[base + tid];

    int arow = tid >> 1, ahalf = tid & 1;
    int brow = tid >> 2, bq = tid & 3;

    auto load_chunk = [&](int kc, int st) {
        uint32_t stg = sbase + OFF_STAGE + st * STAGE_SZ;
        const char* ah = (const char*)(g_Acat + (size_t)(base + arow) * H2 + kc * 32) + ahalf * 32;
        uint32_t boff = arow * 64 + ahalf * 32;
        cpa16(stg + ST_A + SWZ64(boff), ah);
        cpa16(stg + ST_A + SWZ64(boff + 16), ah + 16);
        const char* wh = (const char*)(g_Wh + (size_t)(by * 64 + brow) * H2 + kc * 32) + bq * 16;
        cpa16(stg + ST_B + brow * B_STRIDE + bq * 16, wh);
        cp_commit();
    };

    float acc[2][4][4];
    #pragma unroll
    for (int mt = 0; mt < 2; mt++)
        #pragma unroll
        for (int nb = 0; nb < 4; nb++)
            #pragma unroll
            for (int r = 0; r < 4; r++) acc[mt][nb][r] = 0.0f;

    load_chunk(0, 0);
    load_chunk(1, 1);
    load_chunk(2, 2);

    for (int kc = 0; kc < 16; kc++) {
        if (kc < 14) cp_wait2(); else if (kc == 14) cp_wait1(); else cp_wait0();
        __syncthreads();
        if (kc < 13) load_chunk(kc + 3, (kc + 3) & 3);

        uint32_t stg = sbase + OFF_STAGE + (kc & 3) * STAGE_SZ;
        #pragma unroll
        for (int ks = 0; ks < 2; ks++) {
            int k0 = ks * 16;
            uint32_t bf[4][2];
            int sel = lane >> 3;
            int rinm = lane & 7;
            #pragma unroll
            for (int p = 0; p < 2; p++) {
                int n = wn * 32 + p * 16 + (sel >> 1) * 8 + rinm;
                uint32_t bptr = stg + ST_B + n * B_STRIDE + k0 * 2 + (sel & 1) * 16;
                ldmatrix4(bf[p * 2][0], bf[p * 2][1], bf[p * 2 + 1][0], bf[p * 2 + 1][1], bptr);
            }
            #pragma unroll
            for (int mt = 0; mt < 2; mt++) {
                int row = wm * 32 + mt * 16 + (lane & 15);
                uint32_t boff = SWZ64((uint32_t)(row * 64 + k0 * 2 + (lane >> 4) * 16));
                uint32_t a0, a1, a2, a3;
                ldmatrix4(a0, a1, a2, a3, stg + ST_A + boff);
                #pragma unroll
                for (int nb = 0; nb < 4; nb++)
                    mma16816(acc[mt][nb][0], acc[mt][nb][1], acc[mt][nb][2], acc[mt][nb][3],
                             a0, a1, a2, a3, bf[nb][0], bf[nb][1]);
            }
        }
    }
    __syncthreads();

    float* gates = (float*)(sp + OFF_STAGE);
    #pragma unroll
    for (int mt = 0; mt < 2; mt++) {
        #pragma unroll
        for (int nb = 0; nb < 4; nb++) {
            int r0 = wm * 32 + mt * 16 + (lane >> 2);
            int c0 = wn * 32 + nb * 8 + ((lane & 3) << 1);
            gates[r0 * GST + c0]           = acc[mt][nb][0];
            gates[r0 * GST + c0 + 1]       = acc[mt][nb][1];
            gates[(r0 + 8) * GST + c0]     = acc[mt][nb][2];
            gates[(r0 + 8) * GST + c0 + 1] = acc[mt][nb][3];
        }
    }
    __syncthreads();

    int hl = tid & 15;
    int hid_g = by * 16 + hl;
    #pragma unroll 4
    for (int it = 0; it < 8; it++) {
        int m = (tid >> 4) + (it << 4);
        int node = base + m;
        float4 gt = *(const float4*)(gates + m * GST + hl * 4);
        float4 xt = *(const float4*)(g_xtabp + (size_t)sty[m] * G4 + by * 64 + hl * 4);
        float ig = gt.x + xt.x;
        float fg = gt.y + xt.y;
        float gg = gt.z + xt.z;
        float og = gt.w + xt.w;
        float co = g_Ccat[(size_t)node * H2 + hid_g];
        float cn = sigm_fast(fg) * co + sigm_fast(ig) * tanh_fast(gg);
        float hn = sigm_fast(og) * tanh_fast(cn);
        out[(size_t)node * H2 + hid_g] = hn;
        if (by < 16) {
            int parent = (node - 1) >> 1;
            int poff = (node & 1) ? 0 : 256;
            g_Acat[(size_t)parent * H2 + poff + hid_g] = __float2half_rn(hn);
            g_Ccat[(size_t)parent * H2 + poff + hid_g] = cn;
        }
    }
}

// ---------------- grid barrier ----------------
__device__ __forceinline__ void grid_bar(int nCTA) {
    __syncthreads();
    if (threadIdx.x == 0) {
        __threadfence();
        unsigned gen = atomicOr(&g_bargen, 0u);
        unsigned arrived = atomicAdd(&g_barcnt, 1u);
        if (arrived == (unsigned)(nCTA - 1)) {
            atomicExch(&g_barcnt, 0u);
            __threadfence();
            atomicAdd(&g_bargen, 1u);
        } else {
            while (atomicOr(&g_bargen, 0u) == gen) { }
        }
    }
    __syncthreads();
}

// ---------------- persistent small-levels kernel: levels 6..0 ----------------
__global__ __launch_bounds__(256, 2) void small_levels_kernel(
    const int* __restrict__ types, float* __restrict__ out) {
    extern __shared__ char sm[];
    uint32_t sb = smem_u32(sm);
    uint32_t* ws = (uint32_t*)(sm + SM_WS);
    float* spart = (float*)(sm + SM_SPART);
    float* sgates = (float*)(sm + SM_SGATES);
    int t = threadIdx.x;
    int slice = blockIdx.x & 31;
    int grp = blockIdx.x >> 5;     // 0..7

    // load W slice once (64 rows x 256 uint32)
    {
        const uint32_t* src = (const uint32_t*)(g_Wh + (size_t)slice * 64 * H2);
        #pragma unroll
        for (int i = t; i < 64 * 256; i += 256) {
            int row = i >> 8, q = i & 255;
            ws[row * WS_STRIDE + q] = src[row * 256 + q];
        }
    }
    __syncthreads();

    int jj = t & 63;
    int kq = t >> 6;

    auto issue_node = [&](int nd, int buf) {
        if (t < 64) {
            cpa16(sb + SM_HB + buf * 1024 + t * 16,
                  (const char*)(g_Acat + (size_t)nd * H2) + t * 16);
        } else if (t < 68) {
            int q = t - 64;
            cpa16(sb + SM_CB + buf * 64 + q * 16,
                  (const char*)(g_Ccat + (size_t)nd * H2 + slice * 16) + q * 16);
        } else if (t < 84) {
            int q = t - 68;
            int tyn = types[nd];
            cpa16(sb + SM_XB + buf * 256 + q * 16,
                  (const char*)(g_xtabp + (size_t)tyn * G4 + slice * 64) + q * 16);
        }
        cp_commit();
    };

    for (int d = 6; d >= 0; d--) {
        int n = 1 << d, s = n - 1;
        int node0 = s + grp;
        int cur = 0;
        if (node0 < s + n) issue_node(node0, 0);
        for (int node = node0; node < s + n; node += NGRP) {
            cp_wait0();
            __syncthreads();
            if (node + NGRP < s + n) issue_node(node + NGRP, cur ^ 1);

            const uint32_t* wrow = ws + jj * WS_STRIDE + kq * 64;
            const uint32_t* hrow = (const uint32_t*)(sm + SM_HB + cur * 1024) + kq * 64;
            float acc = 0.0f;
            #pragma unroll 8
            for (int kk = 0; kk < 64; kk++) {
                float2 wf = __half22float2(*(const __half2*)&wrow[kk]);
                float2 hf = __half22float2(*(const __half2*)&hrow[kk]);
                acc = fmaf(wf.x, hf.x, acc);
                acc = fmaf(wf.y, hf.y, acc);
            }
            spart[t] = acc;
            __syncthreads();
            if (t < 64) {
                const float* xb = (const float*)(sm + SM_XB + cur * 256);
                sgates[t] = spart[t] + spart[64 + t] + spart[128 + t] + spart[192 + t] + xb[t];
            }
            __syncthreads();
            if (t < 16) {
                int hid_g = slice * 16 + t;
                const float* cb = (const float*)(sm + SM_CB + cur * 64);
                float ig = sgates[t * 4 + 0];
                float fg = sgates[t * 4 + 1];
                float gg = sgates[t * 4 + 2];
                float og = sgates[t * 4 + 3];
                float co = cb[t];
                float cn = sigm_fast(fg) * co + sigm_fast(ig) * tanh_fast(gg);
                float hn = sigm_fast(og) * tanh_fast(cn);
                out[(size_t)node * H2 + hid_g] = hn;
                if (hid_g < HDIM && node > 0) {
                    int parent = (node - 1) >> 1;
                    int poff = (node & 1) ? 0 : 256;
                    g_Acat[(size_t)parent * H2 + poff + hid_g] = __float2half_rn(hn);
                    g_Ccat[(size_t)parent * H2 + poff + hid_g] = cn;
                }
            }
            cur ^= 1;
        }
        if (d > 0) grid_bar(gridDim.x);
    }
}

extern "C" void kernel_launch(void* const* d_in, const int* in_sizes, int n_in,
                              void* d_out, int out_size) {
    const int* types  = (const int*)d_in[0];
    const float* emb  = (const float*)d_in[3];
    const float* W_ih = (const float*)d_in[4];
    const float* W_hh = (const float*)d_in[5];
    const float* b_ih = (const float*)d_in[6];
    const float* b_hh = (const float*)d_in[7];
    float* out = (float*)d_out;

    cudaFuncSetAttribute(tc_level_kernel, cudaFuncAttributeMaxDynamicSharedMemorySize, SMEM_DYN);
    cudaFuncSetAttribute(small_levels_kernel, cudaFuncAttributeMaxDynamicSharedMemorySize, SMEM_SMALL);

    // #1 xtab, #2 wprep, #3 leaf, #4 = tc13 (profiled)
    xtab_kernel<<<VOCAB, 256>>>(emb, W_ih, b_ih, b_hh);
    wprep_kernel<<<dim3(G4 / 32, H2 / 32), dim3(32, 8)>>>(W_hh);
    leaf_kernel<<<2048, 256>>>(types, out);

    for (int d = 13; d >= 7; d--) {
        int n = 1 << d;
        int s = n - 1;
        tc_level_kernel<<<dim3(n / 128, 32), 256, SMEM_DYN>>>(types, out, s);
    }
    small_levels_kernel<<<256, 256, SMEM_SMALL>>>(types, out);
}